// round 16
// baseline (speedup 1.0000x reference)
#include <cuda_runtime.h>
#include <cuda_bf16.h>
#include <math.h>
#include <stdint.h>

#define N_NODES   100000
#define N_EDGES   1600000
#define IN_FEAT   512
#define HIDDEN    64
#define N_CLASSES 40
#define N_LAYERS  6

#define SCAN_NB   98   // ceil(100000/1024)

// ---------------- device scratch ----------------
__device__ float g_lin[N_NODES * HIDDEN];
__device__ float g_h  [N_NODES * HIDDEN];
__device__ float g_jk [N_NODES * HIDDEN];
__device__ float g_dinv[N_NODES];
__device__ int   g_deg [N_NODES];
__device__ int   g_off [N_NODES + 1];
__device__ int   g_cur [N_NODES];
__device__ int   g_blk [SCAN_NB];
__device__ int   g_blkpref[SCAN_NB];
__device__ __align__(16) int   g_csr_src[N_EDGES];
__device__ __align__(16) float g_csr_w  [N_EDGES];

// ---------------- degree ----------------
__global__ void k_deg_init() {
    int i = blockIdx.x * blockDim.x + threadIdx.x;
    if (i < N_NODES) g_deg[i] = 1;   // self loop
}

__global__ void k_deg_count(const int* __restrict__ dst) {
    int e = blockIdx.x * blockDim.x + threadIdx.x;
    if (e < N_EDGES) atomicAdd(&g_deg[dst[e]], 1);
}

// ---------------- scan of (deg-1) -> CSR offsets; also computes dinv ------
__global__ void k_scan1() {
    __shared__ int sh[1024];
    int i = blockIdx.x * 1024 + threadIdx.x;
    int deg = (i < N_NODES) ? g_deg[i] : 1;
    if (i < N_NODES) g_dinv[i] = rsqrtf((float)deg);
    int v = (i < N_NODES) ? (deg - 1) : 0;
    sh[threadIdx.x] = v;
    __syncthreads();
#pragma unroll
    for (int o = 1; o < 1024; o <<= 1) {
        int t = (threadIdx.x >= o) ? sh[threadIdx.x - o] : 0;
        __syncthreads();
        sh[threadIdx.x] += t;
        __syncthreads();
    }
    if (i < N_NODES) g_off[i] = sh[threadIdx.x] - v;   // exclusive, intra-block
    if (threadIdx.x == 1023) g_blk[blockIdx.x] = sh[1023];
}

__global__ void k_scan2() {
    __shared__ int sh[SCAN_NB];
    if (threadIdx.x < SCAN_NB) sh[threadIdx.x] = g_blk[threadIdx.x];
    __syncthreads();
    if (threadIdx.x == 0) {
        int run = 0;
        for (int b = 0; b < SCAN_NB; b++) { int t = sh[b]; sh[b] = run; run += t; }
        g_off[N_NODES] = N_EDGES;
    }
    __syncthreads();
    if (threadIdx.x < SCAN_NB) g_blkpref[threadIdx.x] = sh[threadIdx.x];
}

__global__ void k_scan3() {
    int i = blockIdx.x * 1024 + threadIdx.x;
    if (i < N_NODES) {
        int o = g_off[i] + g_blkpref[blockIdx.x];
        g_off[i] = o;
        g_cur[i] = o;
    }
}

__global__ void k_fill(const int* __restrict__ src, const int* __restrict__ dst) {
    int e = blockIdx.x * blockDim.x + threadIdx.x;
    if (e < N_EDGES) {
        int s = src[e], d = dst[e];
        int p = atomicAdd(&g_cur[d], 1);
        g_csr_src[p] = s;
        g_csr_w[p]   = g_dinv[s] * g_dinv[d];
    }
}

// =========== mma.sync tf32x3 GEMM: g_lin[N,64] = A[N,K] @ W[K,64] ===========
// 64x64 block tile, 128 threads (4 warps). Warp = rows warp*16..+15 x 64 cols
// (8 m16n8k8 tiles). K chunks of 32, double-buffered via cp.async.
// Smem raw fp32 (A pitch 36, B pitch 72 — conflict-free); hi/lo in-register.
// tf32x3: D += Ahi*Bhi + Alo*Bhi + Ahi*Blo.

__device__ __forceinline__ void mma_tf32(float d[4],
                                         uint32_t a0, uint32_t a1, uint32_t a2, uint32_t a3,
                                         uint32_t b0, uint32_t b1) {
    asm("mma.sync.aligned.m16n8k8.row.col.f32.tf32.tf32.f32 "
        "{%0,%1,%2,%3}, {%4,%5,%6,%7}, {%8,%9}, {%0,%1,%2,%3};"
        : "+f"(d[0]), "+f"(d[1]), "+f"(d[2]), "+f"(d[3])
        : "r"(a0), "r"(a1), "r"(a2), "r"(a3), "r"(b0), "r"(b1));
}

__device__ __forceinline__ float trunc_hi(float x) {
    return __uint_as_float(__float_as_uint(x) & 0xFFFFE000u);
}

__device__ __forceinline__ void cp16(void* smem, const void* gmem, int valid) {
    uint32_t s = (uint32_t)__cvta_generic_to_shared(smem);
    asm volatile("cp.async.cg.shared.global [%0], [%1], 16, %2;"
                 :: "r"(s), "l"(gmem), "r"(valid ? 16 : 0));
}
#define CP_COMMIT() asm volatile("cp.async.commit_group;" ::: "memory")
#define CP_WAIT0()  asm volatile("cp.async.wait_group 0;" ::: "memory")

template <int K, int FROM_H>
__global__ void __launch_bounds__(128)
k_gemm_mma(const float* __restrict__ A, const float* __restrict__ W) {
    __shared__ __align__(16) float As[2][64][36];   // [buf][row][k] raw fp32
    __shared__ __align__(16) float Bs[2][32][72];   // [buf][k][n]   raw fp32

    const float* __restrict__ Asrc = FROM_H ? (const float*)g_h : A;

    const int tid  = threadIdx.x;
    const int warp = tid >> 5;
    const int lane = tid & 31;
    const int g    = lane >> 2;      // group id (0..7)
    const int tg   = lane & 3;       // thread in group
    const int row0 = blockIdx.x * 64;
    constexpr int NCHUNK = K / 32;

    float d[8][4];
#pragma unroll
    for (int t = 0; t < 8; t++)
#pragma unroll
        for (int c = 0; c < 4; c++) d[t][c] = 0.f;

    const int ar0 = warp * 16 + g;
    const int ar1 = ar0 + 8;

    auto stage = [&](int c) {
        const int kc = c * 32, buf = c & 1;
#pragma unroll
        for (int i = 0; i < 4; i++) {
            int idx = tid + i * 128;            // 0..511
            int r = idx >> 3, q = idx & 7;
            int gr = row0 + r;
            int ok = gr < N_NODES;
            int gsafe = ok ? gr : 0;
            cp16(&As[buf][r][q * 4],
                 &Asrc[(size_t)gsafe * K + kc + q * 4], ok);
        }
#pragma unroll
        for (int i = 0; i < 4; i++) {
            int idx = tid + i * 128;            // 0..511
            int k = idx >> 4, n4 = idx & 15;
            cp16(&Bs[buf][k][n4 * 4],
                 &W[(size_t)(kc + k) * 64 + n4 * 4], 1);
        }
        CP_COMMIT();
    };

    stage(0);

    for (int c = 0; c < NCHUNK; c++) {
        const int buf = c & 1;
        CP_WAIT0();
        __syncthreads();
        if (c + 1 < NCHUNK) stage(c + 1);

#pragma unroll
        for (int k8 = 0; k8 < 32; k8 += 8) {
            float a0 = As[buf][ar0][k8 + tg];
            float a1 = As[buf][ar1][k8 + tg];
            float a2 = As[buf][ar0][k8 + tg + 4];
            float a3 = As[buf][ar1][k8 + tg + 4];
            float t0 = trunc_hi(a0), t1 = trunc_hi(a1);
            float t2 = trunc_hi(a2), t3 = trunc_hi(a3);
            uint32_t ah0 = __float_as_uint(t0), ah1 = __float_as_uint(t1);
            uint32_t ah2 = __float_as_uint(t2), ah3 = __float_as_uint(t3);
            uint32_t al0 = __float_as_uint(a0 - t0), al1 = __float_as_uint(a1 - t1);
            uint32_t al2 = __float_as_uint(a2 - t2), al3 = __float_as_uint(a3 - t3);
#pragma unroll
            for (int nt = 0; nt < 8; nt++) {
                int bc = nt * 8 + g;
                float b0 = Bs[buf][k8 + tg][bc];
                float b1 = Bs[buf][k8 + tg + 4][bc];
                float u0 = trunc_hi(b0), u1 = trunc_hi(b1);
                uint32_t bh0 = __float_as_uint(u0), bh1 = __float_as_uint(u1);
                uint32_t bl0 = __float_as_uint(b0 - u0), bl1 = __float_as_uint(b1 - u1);
                mma_tf32(d[nt], ah0, ah1, ah2, ah3, bh0, bh1);   // hi*hi
                mma_tf32(d[nt], al0, al1, al2, al3, bh0, bh1);   // lo*hi
                mma_tf32(d[nt], ah0, ah1, ah2, ah3, bl0, bl1);   // hi*lo
            }
        }
    }

    const int r0 = row0 + warp * 16 + g;
    const int r1 = r0 + 8;
#pragma unroll
    for (int nt = 0; nt < 8; nt++) {
        int col = nt * 8 + 2 * tg;
        if (r0 < N_NODES)
            *(float2*)&g_lin[(size_t)r0 * 64 + col] = make_float2(d[nt][0], d[nt][1]);
        if (r1 < N_NODES)
            *(float2*)&g_lin[(size_t)r1 * 64 + col] = make_float2(d[nt][2], d[nt][3]);
    }
}

// ---------------- fused aggregation: selfloop + CSR gather + bias/relu/jk ----
// One warp per node, float2 per lane. Index/weight loads VECTORIZED (int4 /
// float4 uniform loads): 2 L1 wavefronts per 4 edges instead of 8.
template <int FIRST, int LAST>
__global__ void k_gather(const float* __restrict__ b) {
    unsigned gw   = (blockIdx.x * blockDim.x + threadIdx.x) >> 5;
    unsigned lane = threadIdx.x & 31;
    if (gw >= N_NODES) return;

    const float2* __restrict__ lin2 = (const float2*)g_lin;
    float dn = g_dinv[gw];
    float2 self = lin2[gw * 32u + lane];
    float2 acc = make_float2(dn * dn * self.x, dn * dn * self.y);

    int j = g_off[gw], end = g_off[gw + 1];

    // head: align j to 4 for int4/float4 loads
    while (j < end && (j & 3)) {
        int s = g_csr_src[j];
        float w = g_csr_w[j];
        float2 m = lin2[(unsigned)s * 32u + lane];
        acc.x = fmaf(w, m.x, acc.x);
        acc.y = fmaf(w, m.y, acc.y);
        j++;
    }
    // main: 4 edges per iteration, vector index/weight loads
    for (; j + 4 <= end; j += 4) {
        int4   s4 = *(const int4*)&g_csr_src[j];
        float4 w4 = *(const float4*)&g_csr_w[j];
        float2 m0 = lin2[(unsigned)s4.x * 32u + lane];
        float2 m1 = lin2[(unsigned)s4.y * 32u + lane];
        float2 m2 = lin2[(unsigned)s4.z * 32u + lane];
        float2 m3 = lin2[(unsigned)s4.w * 32u + lane];
        acc.x = fmaf(w4.x, m0.x, fmaf(w4.y, m1.x, fmaf(w4.z, m2.x, fmaf(w4.w, m3.x, acc.x))));
        acc.y = fmaf(w4.x, m0.y, fmaf(w4.y, m1.y, fmaf(w4.z, m2.y, fmaf(w4.w, m3.y, acc.y))));
    }
    // tail
    for (; j < end; j++) {
        int s = g_csr_src[j];
        float w = g_csr_w[j];
        float2 m = lin2[(unsigned)s * 32u + lane];
        acc.x = fmaf(w, m.x, acc.x);
        acc.y = fmaf(w, m.y, acc.y);
    }

    float vx = fmaxf(acc.x + b[lane * 2],     0.f);
    float vy = fmaxf(acc.y + b[lane * 2 + 1], 0.f);
    if (!LAST)
        ((float2*)g_h)[gw * 32u + lane] = make_float2(vx, vy);
    float2* jk2 = (float2*)g_jk;
    if (FIRST) {
        jk2[gw * 32u + lane] = make_float2(vx, vy);
    } else {
        float2 o = jk2[gw * 32u + lane];
        jk2[gw * 32u + lane] = make_float2(fmaxf(o.x, vx), fmaxf(o.y, vy));
    }
}

// ---------------- final: logits = jk @ fcW + fcb; log_softmax ----------------
// 256 threads; block processes 16 nodes (4 passes of 4) reusing Wf in smem.
__global__ void k_final(const float* __restrict__ fcW,
                        const float* __restrict__ fcb,
                        float* __restrict__ out) {
    __shared__ float Wf[HIDDEN * N_CLASSES];
    __shared__ float row[4][HIDDEN];
    __shared__ float logits[4][N_CLASSES];
    __shared__ float lse[4];

    for (int i = threadIdx.x; i < HIDDEN * N_CLASSES; i += 256)
        Wf[i] = fcW[i];

    const int g = threadIdx.x >> 6;
    const int f = threadIdx.x & 63;

    for (int pass = 0; pass < 4; pass++) {
        const int node = blockIdx.x * 16 + pass * 4 + g;
        __syncthreads();

        if (node < N_NODES)
            row[g][f] = g_jk[(size_t)node * HIDDEN + f];
        __syncthreads();

        if (node < N_NODES && f < N_CLASSES) {
            float acc = fcb[f];
#pragma unroll
            for (int h = 0; h < HIDDEN; h++)
                acc = fmaf(row[g][h], Wf[h * N_CLASSES + f], acc);
            logits[g][f] = acc;
        }
        __syncthreads();

        if (node < N_NODES && f == 0) {
            float m = -INFINITY;
#pragma unroll
            for (int c = 0; c < N_CLASSES; c++) m = fmaxf(m, logits[g][c]);
            float s = 0.f;
#pragma unroll
            for (int c = 0; c < N_CLASSES; c++) s += expf(logits[g][c] - m);
            lse[g] = m + logf(s);
        }
        __syncthreads();

        if (node < N_NODES && f < N_CLASSES)
            out[(size_t)node * N_CLASSES + f] = logits[g][f] - lse[g];
    }
}

// ---------------- launch ----------------
extern "C" void kernel_launch(void* const* d_in, const int* in_sizes, int n_in,
                              void* d_out, int out_size) {
    const float* x      = (const float*)d_in[0];
    const int*   edge   = (const int*)d_in[1];     // int64 lowered to int32
    const float* W0     = (const float*)d_in[2];
    const float* b0     = (const float*)d_in[3];
    const float* W_rest = (const float*)d_in[4];
    const float* b_rest = (const float*)d_in[5];
    const float* fcW    = (const float*)d_in[6];
    const float* fcb    = (const float*)d_in[7];
    float* out = (float*)d_out;

    const int* src = edge;
    const int* dst = edge + N_EDGES;

    const int EB = (N_EDGES + 255) / 256;          // 6250
    const int NB = (N_NODES + 255) / 256;
    const int GB = (N_NODES + 63) / 64;            // 1563
    const int AB = (N_NODES * 32 + 255) / 256;     // 12500 (warp per node)

    // launch index 3 gets profiled by ncu -> big GEMM stays there.
    k_deg_init <<<NB, 256>>>();                         // 0
    k_deg_count<<<EB, 256>>>(dst);                      // 1
    k_scan1    <<<SCAN_NB, 1024>>>();                   // 2 (also dinv)
    k_gemm_mma<IN_FEAT, 0><<<GB, 128>>>(x, W0);         // 3  <- profiled
    k_scan2    <<<1, 128>>>();                          // 4
    k_scan3    <<<SCAN_NB, 1024>>>();                   // 5
    k_fill     <<<EB, 256>>>(src, dst);                 // 6

    // layer 0 aggregation
    k_gather<1, 0><<<AB, 256>>>(b0);

    // layers 1..5
    for (int l = 0; l < N_LAYERS - 1; l++) {
        k_gemm_mma<HIDDEN, 1><<<GB, 128>>>(nullptr, W_rest + (size_t)l * HIDDEN * HIDDEN);
        if (l < N_LAYERS - 2)
            k_gather<0, 0><<<AB, 256>>>(b_rest + (size_t)l * HIDDEN);
        else
            k_gather<0, 1><<<AB, 256>>>(b_rest + (size_t)l * HIDDEN);
    }

    // final FC + log_softmax
    k_final<<<(N_NODES + 15) / 16, 256>>>(fcW, fcb, out);
}

// round 17
// speedup vs baseline: 1.0346x; 1.0346x over previous
#include <cuda_runtime.h>
#include <cuda_bf16.h>
#include <math.h>
#include <stdint.h>

#define N_NODES   100000
#define N_EDGES   1600000
#define IN_FEAT   512
#define HIDDEN    64
#define N_CLASSES 40
#define N_LAYERS  6

#define SCAN_NB   98   // ceil(100000/1024)

// ---------------- device scratch ----------------
__device__ float g_lin[N_NODES * HIDDEN];
__device__ float g_h  [N_NODES * HIDDEN];
__device__ float g_jk [N_NODES * HIDDEN];
__device__ float g_dinv[N_NODES];
__device__ int   g_deg [N_NODES];
__device__ int   g_off [N_NODES + 1];
__device__ int   g_cur [N_NODES];
__device__ int   g_blk [SCAN_NB];
__device__ int   g_blkpref[SCAN_NB];
__device__ __align__(16) int2 g_csr[N_EDGES];   // packed {src, w-as-int}

// ---------------- degree ----------------
__global__ void k_deg_init() {
    int i = blockIdx.x * blockDim.x + threadIdx.x;
    if (i < N_NODES) g_deg[i] = 1;   // self loop
}

__global__ void k_deg_count(const int* __restrict__ dst) {
    int e = blockIdx.x * blockDim.x + threadIdx.x;
    if (e < N_EDGES) atomicAdd(&g_deg[dst[e]], 1);
}

// ---------------- scan of (deg-1) -> CSR offsets; also computes dinv ------
__global__ void k_scan1() {
    __shared__ int sh[1024];
    int i = blockIdx.x * 1024 + threadIdx.x;
    int deg = (i < N_NODES) ? g_deg[i] : 1;
    if (i < N_NODES) g_dinv[i] = rsqrtf((float)deg);
    int v = (i < N_NODES) ? (deg - 1) : 0;
    sh[threadIdx.x] = v;
    __syncthreads();
#pragma unroll
    for (int o = 1; o < 1024; o <<= 1) {
        int t = (threadIdx.x >= o) ? sh[threadIdx.x - o] : 0;
        __syncthreads();
        sh[threadIdx.x] += t;
        __syncthreads();
    }
    if (i < N_NODES) g_off[i] = sh[threadIdx.x] - v;   // exclusive, intra-block
    if (threadIdx.x == 1023) g_blk[blockIdx.x] = sh[1023];
}

__global__ void k_scan2() {
    __shared__ int sh[SCAN_NB];
    if (threadIdx.x < SCAN_NB) sh[threadIdx.x] = g_blk[threadIdx.x];
    __syncthreads();
    if (threadIdx.x == 0) {
        int run = 0;
        for (int b = 0; b < SCAN_NB; b++) { int t = sh[b]; sh[b] = run; run += t; }
        g_off[N_NODES] = N_EDGES;
    }
    __syncthreads();
    if (threadIdx.x < SCAN_NB) g_blkpref[threadIdx.x] = sh[threadIdx.x];
}

__global__ void k_scan3() {
    int i = blockIdx.x * 1024 + threadIdx.x;
    if (i < N_NODES) {
        int o = g_off[i] + g_blkpref[blockIdx.x];
        g_off[i] = o;
        g_cur[i] = o;
    }
}

__global__ void k_fill(const int* __restrict__ src, const int* __restrict__ dst) {
    int e = blockIdx.x * blockDim.x + threadIdx.x;
    if (e < N_EDGES) {
        int s = src[e], d = dst[e];
        int p = atomicAdd(&g_cur[d], 1);
        float w = g_dinv[s] * g_dinv[d];
        g_csr[p] = make_int2(s, __float_as_int(w));   // single STG.64 scatter
    }
}

// =========== mma.sync tf32x3 GEMM: g_lin[N,64] = A[N,K] @ W[K,64] ===========
// 64x64 block tile, 128 threads (4 warps). Warp = rows warp*16..+15 x 64 cols
// (8 m16n8k8 tiles). K chunks of 32, double-buffered via cp.async.
// Smem raw fp32 (A pitch 36, B pitch 72 — conflict-free); hi/lo in-register.
// tf32x3: D += Ahi*Bhi + Alo*Bhi + Ahi*Blo.

__device__ __forceinline__ void mma_tf32(float d[4],
                                         uint32_t a0, uint32_t a1, uint32_t a2, uint32_t a3,
                                         uint32_t b0, uint32_t b1) {
    asm("mma.sync.aligned.m16n8k8.row.col.f32.tf32.tf32.f32 "
        "{%0,%1,%2,%3}, {%4,%5,%6,%7}, {%8,%9}, {%0,%1,%2,%3};"
        : "+f"(d[0]), "+f"(d[1]), "+f"(d[2]), "+f"(d[3])
        : "r"(a0), "r"(a1), "r"(a2), "r"(a3), "r"(b0), "r"(b1));
}

__device__ __forceinline__ float trunc_hi(float x) {
    return __uint_as_float(__float_as_uint(x) & 0xFFFFE000u);
}

__device__ __forceinline__ void cp16(void* smem, const void* gmem, int valid) {
    uint32_t s = (uint32_t)__cvta_generic_to_shared(smem);
    asm volatile("cp.async.cg.shared.global [%0], [%1], 16, %2;"
                 :: "r"(s), "l"(gmem), "r"(valid ? 16 : 0));
}
#define CP_COMMIT() asm volatile("cp.async.commit_group;" ::: "memory")
#define CP_WAIT0()  asm volatile("cp.async.wait_group 0;" ::: "memory")

template <int K, int FROM_H>
__global__ void __launch_bounds__(128)
k_gemm_mma(const float* __restrict__ A, const float* __restrict__ W) {
    __shared__ __align__(16) float As[2][64][36];   // [buf][row][k] raw fp32
    __shared__ __align__(16) float Bs[2][32][72];   // [buf][k][n]   raw fp32

    const float* __restrict__ Asrc = FROM_H ? (const float*)g_h : A;

    const int tid  = threadIdx.x;
    const int warp = tid >> 5;
    const int lane = tid & 31;
    const int g    = lane >> 2;      // group id (0..7)
    const int tg   = lane & 3;       // thread in group
    const int row0 = blockIdx.x * 64;
    constexpr int NCHUNK = K / 32;

    float d[8][4];
#pragma unroll
    for (int t = 0; t < 8; t++)
#pragma unroll
        for (int c = 0; c < 4; c++) d[t][c] = 0.f;

    const int ar0 = warp * 16 + g;
    const int ar1 = ar0 + 8;

    auto stage = [&](int c) {
        const int kc = c * 32, buf = c & 1;
#pragma unroll
        for (int i = 0; i < 4; i++) {
            int idx = tid + i * 128;            // 0..511
            int r = idx >> 3, q = idx & 7;
            int gr = row0 + r;
            int ok = gr < N_NODES;
            int gsafe = ok ? gr : 0;
            cp16(&As[buf][r][q * 4],
                 &Asrc[(size_t)gsafe * K + kc + q * 4], ok);
        }
#pragma unroll
        for (int i = 0; i < 4; i++) {
            int idx = tid + i * 128;            // 0..511
            int k = idx >> 4, n4 = idx & 15;
            cp16(&Bs[buf][k][n4 * 4],
                 &W[(size_t)(kc + k) * 64 + n4 * 4], 1);
        }
        CP_COMMIT();
    };

    stage(0);

    for (int c = 0; c < NCHUNK; c++) {
        const int buf = c & 1;
        CP_WAIT0();
        __syncthreads();
        if (c + 1 < NCHUNK) stage(c + 1);

#pragma unroll
        for (int k8 = 0; k8 < 32; k8 += 8) {
            float a0 = As[buf][ar0][k8 + tg];
            float a1 = As[buf][ar1][k8 + tg];
            float a2 = As[buf][ar0][k8 + tg + 4];
            float a3 = As[buf][ar1][k8 + tg + 4];
            float t0 = trunc_hi(a0), t1 = trunc_hi(a1);
            float t2 = trunc_hi(a2), t3 = trunc_hi(a3);
            uint32_t ah0 = __float_as_uint(t0), ah1 = __float_as_uint(t1);
            uint32_t ah2 = __float_as_uint(t2), ah3 = __float_as_uint(t3);
            uint32_t al0 = __float_as_uint(a0 - t0), al1 = __float_as_uint(a1 - t1);
            uint32_t al2 = __float_as_uint(a2 - t2), al3 = __float_as_uint(a3 - t3);
#pragma unroll
            for (int nt = 0; nt < 8; nt++) {
                int bc = nt * 8 + g;
                float b0 = Bs[buf][k8 + tg][bc];
                float b1 = Bs[buf][k8 + tg + 4][bc];
                float u0 = trunc_hi(b0), u1 = trunc_hi(b1);
                uint32_t bh0 = __float_as_uint(u0), bh1 = __float_as_uint(u1);
                uint32_t bl0 = __float_as_uint(b0 - u0), bl1 = __float_as_uint(b1 - u1);
                mma_tf32(d[nt], ah0, ah1, ah2, ah3, bh0, bh1);   // hi*hi
                mma_tf32(d[nt], al0, al1, al2, al3, bh0, bh1);   // lo*hi
                mma_tf32(d[nt], ah0, ah1, ah2, ah3, bl0, bl1);   // hi*lo
            }
        }
    }

    const int r0 = row0 + warp * 16 + g;
    const int r1 = r0 + 8;
#pragma unroll
    for (int nt = 0; nt < 8; nt++) {
        int col = nt * 8 + 2 * tg;
        if (r0 < N_NODES)
            *(float2*)&g_lin[(size_t)r0 * 64 + col] = make_float2(d[nt][0], d[nt][1]);
        if (r1 < N_NODES)
            *(float2*)&g_lin[(size_t)r1 * 64 + col] = make_float2(d[nt][2], d[nt][3]);
    }
}

// ---------------- fused aggregation: selfloop + CSR gather + bias/relu/jk ----
// One warp per node, float2 per lane. R15 loop shape (4 independent edge loads
// per iteration) with PACKED int2 {src, w}: one 8B broadcast per edge instead
// of two 4B broadcasts.
template <int FIRST, int LAST>
__global__ void k_gather(const float* __restrict__ b) {
    unsigned gw   = (blockIdx.x * blockDim.x + threadIdx.x) >> 5;
    unsigned lane = threadIdx.x & 31;
    if (gw >= N_NODES) return;

    const float2* __restrict__ lin2 = (const float2*)g_lin;
    float dn = g_dinv[gw];
    float2 self = lin2[gw * 32u + lane];
    float2 acc = make_float2(dn * dn * self.x, dn * dn * self.y);

    int j = g_off[gw], end = g_off[gw + 1];
    for (; j + 4 <= end; j += 4) {
        int2 e0 = g_csr[j],     e1 = g_csr[j + 1];
        int2 e2 = g_csr[j + 2], e3 = g_csr[j + 3];
        float2 m0 = lin2[(unsigned)e0.x * 32u + lane];
        float2 m1 = lin2[(unsigned)e1.x * 32u + lane];
        float2 m2 = lin2[(unsigned)e2.x * 32u + lane];
        float2 m3 = lin2[(unsigned)e3.x * 32u + lane];
        float w0 = __int_as_float(e0.y), w1 = __int_as_float(e1.y);
        float w2 = __int_as_float(e2.y), w3 = __int_as_float(e3.y);
        acc.x = fmaf(w0, m0.x, fmaf(w1, m1.x, fmaf(w2, m2.x, fmaf(w3, m3.x, acc.x))));
        acc.y = fmaf(w0, m0.y, fmaf(w1, m1.y, fmaf(w2, m2.y, fmaf(w3, m3.y, acc.y))));
    }
    for (; j < end; j++) {
        int2 e = g_csr[j];
        float w = __int_as_float(e.y);
        float2 m = lin2[(unsigned)e.x * 32u + lane];
        acc.x = fmaf(w, m.x, acc.x);
        acc.y = fmaf(w, m.y, acc.y);
    }

    float vx = fmaxf(acc.x + b[lane * 2],     0.f);
    float vy = fmaxf(acc.y + b[lane * 2 + 1], 0.f);
    if (!LAST)
        ((float2*)g_h)[gw * 32u + lane] = make_float2(vx, vy);
    float2* jk2 = (float2*)g_jk;
    if (FIRST) {
        jk2[gw * 32u + lane] = make_float2(vx, vy);
    } else {
        float2 o = jk2[gw * 32u + lane];
        jk2[gw * 32u + lane] = make_float2(fmaxf(o.x, vx), fmaxf(o.y, vy));
    }
}

// ---------------- final: logits = jk @ fcW + fcb; log_softmax ----------------
// 256 threads; block processes 16 nodes (4 passes of 4) reusing Wf in smem.
__global__ void k_final(const float* __restrict__ fcW,
                        const float* __restrict__ fcb,
                        float* __restrict__ out) {
    __shared__ float Wf[HIDDEN * N_CLASSES];
    __shared__ float row[4][HIDDEN];
    __shared__ float logits[4][N_CLASSES];
    __shared__ float lse[4];

    for (int i = threadIdx.x; i < HIDDEN * N_CLASSES; i += 256)
        Wf[i] = fcW[i];

    const int g = threadIdx.x >> 6;
    const int f = threadIdx.x & 63;

    for (int pass = 0; pass < 4; pass++) {
        const int node = blockIdx.x * 16 + pass * 4 + g;
        __syncthreads();

        if (node < N_NODES)
            row[g][f] = g_jk[(size_t)node * HIDDEN + f];
        __syncthreads();

        if (node < N_NODES && f < N_CLASSES) {
            float acc = fcb[f];
#pragma unroll
            for (int h = 0; h < HIDDEN; h++)
                acc = fmaf(row[g][h], Wf[h * N_CLASSES + f], acc);
            logits[g][f] = acc;
        }
        __syncthreads();

        if (node < N_NODES && f == 0) {
            float m = -INFINITY;
#pragma unroll
            for (int c = 0; c < N_CLASSES; c++) m = fmaxf(m, logits[g][c]);
            float s = 0.f;
#pragma unroll
            for (int c = 0; c < N_CLASSES; c++) s += expf(logits[g][c] - m);
            lse[g] = m + logf(s);
        }
        __syncthreads();

        if (node < N_NODES && f < N_CLASSES)
            out[(size_t)node * N_CLASSES + f] = logits[g][f] - lse[g];
    }
}

// ---------------- launch ----------------
extern "C" void kernel_launch(void* const* d_in, const int* in_sizes, int n_in,
                              void* d_out, int out_size) {
    const float* x      = (const float*)d_in[0];
    const int*   edge   = (const int*)d_in[1];     // int64 lowered to int32
    const float* W0     = (const float*)d_in[2];
    const float* b0     = (const float*)d_in[3];
    const float* W_rest = (const float*)d_in[4];
    const float* b_rest = (const float*)d_in[5];
    const float* fcW    = (const float*)d_in[6];
    const float* fcb    = (const float*)d_in[7];
    float* out = (float*)d_out;

    const int* src = edge;
    const int* dst = edge + N_EDGES;

    const int EB = (N_EDGES + 255) / 256;          // 6250
    const int NB = (N_NODES + 255) / 256;
    const int GB = (N_NODES + 63) / 64;            // 1563
    const int AB = (N_NODES * 32 + 255) / 256;     // 12500 (warp per node)

    // launch index 3 gets profiled by ncu -> big GEMM stays there.
    k_deg_init <<<NB, 256>>>();                         // 0
    k_deg_count<<<EB, 256>>>(dst);                      // 1
    k_scan1    <<<SCAN_NB, 1024>>>();                   // 2 (also dinv)
    k_gemm_mma<IN_FEAT, 0><<<GB, 128>>>(x, W0);         // 3  <- profiled
    k_scan2    <<<1, 128>>>();                          // 4
    k_scan3    <<<SCAN_NB, 1024>>>();                   // 5
    k_fill     <<<EB, 256>>>(src, dst);                 // 6

    // layer 0 aggregation
    k_gather<1, 0><<<AB, 256>>>(b0);

    // layers 1..5
    for (int l = 0; l < N_LAYERS - 1; l++) {
        k_gemm_mma<HIDDEN, 1><<<GB, 128>>>(nullptr, W_rest + (size_t)l * HIDDEN * HIDDEN);
        if (l < N_LAYERS - 2)
            k_gather<0, 0><<<AB, 256>>>(b_rest + (size_t)l * HIDDEN);
        else
            k_gather<0, 1><<<AB, 256>>>(b_rest + (size_t)l * HIDDEN);
    }

    // final FC + log_softmax
    k_final<<<(N_NODES + 15) / 16, 256>>>(fcW, fcb, out);
}